// round 3
// baseline (speedup 1.0000x reference)
#include <cuda_runtime.h>

#define BB 8
#define CC 512
#define DD 64
#define NN 16384
#define PARAM 10.0f
#define EPS 1e-6f
#define NSPLIT 16

// Scratch (device globals: allocation-free)
__device__ float g_Q[BB * DD * NN];      // phi(Q)  [b, m, n]
__device__ float g_K[BB * DD * NN];      // phi(K)  [b, m, n]
__device__ float g_Ksum[BB * DD];        // sum_n phi(K)
__device__ float g_KX[BB * DD * CC];     // phi(K) @ x^T
__device__ float g_KV[BB * DD * CC];     // KX @ Wv^T + bv * Ksum

__device__ __forceinline__ float fmap(float t) {
    // 10*relu(t) + exp(10*min(t,0)):  t>0 -> 10t+1 ; t<=0 -> exp(10t)
    return t > 0.f ? fmaf(PARAM, t, 1.f) : __expf(PARAM * t);
}

// ---------------------------------------------------------------------------
// Kernel 0: zero accumulators
// ---------------------------------------------------------------------------
__global__ void k_zero() {
    int i = blockIdx.x * blockDim.x + threadIdx.x;
    if (i < BB * DD * CC) g_KX[i] = 0.f;
    if (i < BB * DD)      g_Ksum[i] = 0.f;
}

// ---------------------------------------------------------------------------
// Kernel 1: fused Q/K projection. [128rows x 512] @ [512 x N] per batch.
// Rows 0..63 = Q (Wq,bq), rows 64..127 = K (Wk,bk). Applies feature map,
// accumulates Ksum via warp-reduced atomics.
// 256 thr, tile 128m x 128n, micro 8x8, float4 LDS/LDG/STG, kchunk=16.
// ---------------------------------------------------------------------------
__global__ __launch_bounds__(256) void k_qk(
        const float* __restrict__ x,
        const float* __restrict__ Wq, const float* __restrict__ bq,
        const float* __restrict__ Wk, const float* __restrict__ bk) {
    __shared__ float As[16][128];  // [k][m]
    __shared__ float Bs[16][128];  // [k][n]
    const int b  = blockIdx.y;
    const int n0 = blockIdx.x * 128;
    const int tid = threadIdx.x;
    const int tx = tid & 15, ty = tid >> 4;
    const float* xb = x + (size_t)b * CC * NN;

    float acc[8][8] = {};
    for (int kc = 0; kc < CC; kc += 16) {
        // As: 128 rows of W (Q|K), cols kc..kc+15, stored [k][m]
        #pragma unroll
        for (int i = 0; i < 2; i++) {
            int idx = tid + i * 256;
            int m  = idx >> 2;            // 0..127
            int c4 = (idx & 3) * 4;       // 0,4,8,12
            const float* Wrow = (m < 64) ? (Wq + m * CC) : (Wk + (m - 64) * CC);
            float4 w = *(const float4*)(Wrow + kc + c4);
            As[c4 + 0][m] = w.x; As[c4 + 1][m] = w.y;
            As[c4 + 2][m] = w.z; As[c4 + 3][m] = w.w;
        }
        // Bs: x tile [k][n], direct float4
        #pragma unroll
        for (int i = 0; i < 2; i++) {
            int idx = tid + i * 256;
            int c  = idx >> 5;            // 0..15
            int n4 = (idx & 31) * 4;      // 0..124
            *(float4*)&Bs[c][n4] =
                *(const float4*)(xb + (size_t)(kc + c) * NN + n0 + n4);
        }
        __syncthreads();
        #pragma unroll
        for (int k = 0; k < 16; k++) {
            float4 a0 = *(float4*)&As[k][ty * 8];
            float4 a1 = *(float4*)&As[k][ty * 8 + 4];
            float4 b0 = *(float4*)&Bs[k][tx * 8];
            float4 b1 = *(float4*)&Bs[k][tx * 8 + 4];
            float a[8] = {a0.x, a0.y, a0.z, a0.w, a1.x, a1.y, a1.z, a1.w};
            float bv[8] = {b0.x, b0.y, b0.z, b0.w, b1.x, b1.y, b1.z, b1.w};
            #pragma unroll
            for (int i = 0; i < 8; i++)
                #pragma unroll
                for (int j = 0; j < 8; j++)
                    acc[i][j] = fmaf(a[i], bv[j], acc[i][j]);
        }
        __syncthreads();
    }

    // Epilogue: ty<8 -> Q rows (m=ty*8+i), ty>=8 -> K rows.
    #pragma unroll
    for (int i = 0; i < 8; i++) {
        const int m = ty * 8 + i;
        if (ty < 8) {
            const float bias = bq[m];
            float v[8];
            #pragma unroll
            for (int j = 0; j < 8; j++) v[j] = fmap(acc[i][j] + bias);
            float* dst = g_Q + ((size_t)b * DD + m) * NN + n0 + tx * 8;
            *(float4*)(dst)     = make_float4(v[0], v[1], v[2], v[3]);
            *(float4*)(dst + 4) = make_float4(v[4], v[5], v[6], v[7]);
        } else {
            const int mm = m - 64;
            const float bias = bk[mm];
            float v[8], rsum = 0.f;
            #pragma unroll
            for (int j = 0; j < 8; j++) { v[j] = fmap(acc[i][j] + bias); rsum += v[j]; }
            float* dst = g_K + ((size_t)b * DD + mm) * NN + n0 + tx * 8;
            *(float4*)(dst)     = make_float4(v[0], v[1], v[2], v[3]);
            *(float4*)(dst + 4) = make_float4(v[4], v[5], v[6], v[7]);
            #pragma unroll
            for (int off = 8; off; off >>= 1)
                rsum += __shfl_down_sync(0xffffffffu, rsum, off, 16);
            if (tx == 0) atomicAdd(&g_Ksum[b * DD + mm], rsum);
        }
    }
}

// ---------------------------------------------------------------------------
// Kernel 2: KX[b,m,c] = sum_n phiK[b,m,n] * x[b,c,n]   (split-K over n)
// 256 thr, tile 64m x 128c, micro 4m x 8c, kchunk=32, float4 everywhere.
// ---------------------------------------------------------------------------
__global__ __launch_bounds__(256) void k_kx(const float* __restrict__ x) {
    __shared__ float Ks[32][68];   // [n][m], padded
    __shared__ float Xs[32][132];  // [n][c], padded
    const int n_base = blockIdx.x * (NN / NSPLIT);   // 1024-wide split
    const int c0 = blockIdx.y * 128;
    const int b  = blockIdx.z;
    const int tid = threadIdx.x;
    const int tx = tid & 15, ty = tid >> 4;

    float acc[4][8] = {};
    for (int kn = 0; kn < NN / NSPLIT; kn += 32) {
        const size_t nb = n_base + kn;
        // Ks: [m][n] gmem -> [n][m] smem (float4 LDG, scalar STS)
        #pragma unroll
        for (int i = 0; i < 2; i++) {
            int idx = tid + i * 256;
            int m   = idx >> 3;           // 0..63
            int nn4 = (idx & 7) * 4;      // 0..28
            float4 kv = *(const float4*)(g_K + ((size_t)b * DD + m) * NN + nb + nn4);
            Ks[nn4 + 0][m] = kv.x; Ks[nn4 + 1][m] = kv.y;
            Ks[nn4 + 2][m] = kv.z; Ks[nn4 + 3][m] = kv.w;
        }
        // Xs: [c][n] gmem -> [n][c] smem
        #pragma unroll
        for (int i = 0; i < 4; i++) {
            int idx = tid + i * 256;
            int c   = idx >> 3;           // 0..127
            int nn4 = (idx & 7) * 4;
            float4 xv = *(const float4*)(x + ((size_t)(b * CC + c0 + c)) * NN + nb + nn4);
            Xs[nn4 + 0][c] = xv.x; Xs[nn4 + 1][c] = xv.y;
            Xs[nn4 + 2][c] = xv.z; Xs[nn4 + 3][c] = xv.w;
        }
        __syncthreads();
        #pragma unroll
        for (int k = 0; k < 32; k++) {
            float4 a  = *(float4*)&Ks[k][ty * 4];
            float4 b0 = *(float4*)&Xs[k][tx * 8];
            float4 b1 = *(float4*)&Xs[k][tx * 8 + 4];
            float av[4] = {a.x, a.y, a.z, a.w};
            float bv[8] = {b0.x, b0.y, b0.z, b0.w, b1.x, b1.y, b1.z, b1.w};
            #pragma unroll
            for (int i = 0; i < 4; i++)
                #pragma unroll
                for (int j = 0; j < 8; j++)
                    acc[i][j] = fmaf(av[i], bv[j], acc[i][j]);
        }
        __syncthreads();
    }
    #pragma unroll
    for (int i = 0; i < 4; i++)
        #pragma unroll
        for (int j = 0; j < 8; j++)
            atomicAdd(&g_KX[((size_t)b * DD + ty * 4 + i) * CC + c0 + tx * 8 + j],
                      acc[i][j]);
}

// ---------------------------------------------------------------------------
// Kernel 3: KV[b,m,c] = sum_{c'} KX[b,m,c'] * Wv[c,c'] + bv[c]*Ksum[b,m]
// Tiny (268 MF). 256 thr, tile 64x64, micro 4x4.
// ---------------------------------------------------------------------------
__global__ void k_kv(const float* __restrict__ Wv, const float* __restrict__ bv) {
    __shared__ float As[32][65];  // [c'][m]
    __shared__ float Ws[32][65];  // [c'][c]
    const int c0 = blockIdx.x * 64;
    const int b  = blockIdx.y;
    const int tid = threadIdx.x;
    const int tx = tid & 15, ty = tid >> 4;

    float acc[4][4] = {};
    for (int kc = 0; kc < CC; kc += 32) {
        {
            int cc = tid & 31;
            #pragma unroll
            for (int m = tid >> 5; m < 64; m += 8)
                As[cc][m] = g_KX[((size_t)b * DD + m) * CC + kc + cc];
            #pragma unroll
            for (int c = tid >> 5; c < 64; c += 8)
                Ws[cc][c] = Wv[(size_t)(c0 + c) * CC + kc + cc];
        }
        __syncthreads();
        #pragma unroll
        for (int k = 0; k < 32; k++) {
            float a[4], w[4];
            #pragma unroll
            for (int i = 0; i < 4; i++) a[i] = As[k][ty + 16 * i];
            #pragma unroll
            for (int j = 0; j < 4; j++) w[j] = Ws[k][tx + 16 * j];
            #pragma unroll
            for (int i = 0; i < 4; i++)
                #pragma unroll
                for (int j = 0; j < 4; j++)
                    acc[i][j] = fmaf(a[i], w[j], acc[i][j]);
        }
        __syncthreads();
    }
    #pragma unroll
    for (int i = 0; i < 4; i++) {
        int m = ty + 16 * i;
        float ks = g_Ksum[b * DD + m];
        #pragma unroll
        for (int j = 0; j < 4; j++) {
            int c = c0 + tx + 16 * j;
            g_KV[((size_t)b * DD + m) * CC + c] = fmaf(bv[c], ks, acc[i][j]);
        }
    }
}

// ---------------------------------------------------------------------------
// Kernel 4: out[b,c,n] = x + gamma * rnorm[n] * sum_m phiQ[m,n]*KV[m,c]
// Fuses the denominator: den[n] = sum_m phiQ[m,n]*(Ksum[m]+eps).
// 256 thr, tile 128n x 128c, micro 8x8, kchunk=32, float4 everywhere.
// ---------------------------------------------------------------------------
__global__ __launch_bounds__(256) void k_out(
        const float* __restrict__ x, const float* __restrict__ gamma,
        float* __restrict__ out) {
    __shared__ float Qs[32][128];    // [m][n]
    __shared__ float KVs[32][128];   // [m][c]
    __shared__ float ksum_s[DD];
    const int c0 = blockIdx.x * 128;   // c fastest: c-tiles of same n share Q in L2
    const int n0 = blockIdx.y * 128;
    const int b  = blockIdx.z;
    const int tid = threadIdx.x;
    const int tx = tid & 15, ty = tid >> 4;

    if (tid < DD) ksum_s[tid] = g_Ksum[b * DD + tid] + EPS;

    float acc[8][8] = {};   // [c][n]
    float den[8] = {};
    for (int m0 = 0; m0 < DD; m0 += 32) {
        __syncthreads();   // also orders ksum_s write before first use
        #pragma unroll
        for (int i = 0; i < 4; i++) {
            int idx = tid + i * 256;
            int m  = idx >> 5;
            int n4 = (idx & 31) * 4;
            *(float4*)&Qs[m][n4] =
                *(const float4*)(g_Q + ((size_t)b * DD + m0 + m) * NN + n0 + n4);
        }
        #pragma unroll
        for (int i = 0; i < 4; i++) {
            int idx = tid + i * 256;
            int m  = idx >> 5;
            int c4 = (idx & 31) * 4;
            *(float4*)&KVs[m][c4] =
                *(const float4*)(g_KV + ((size_t)b * DD + m0 + m) * CC + c0 + c4);
        }
        __syncthreads();
        #pragma unroll
        for (int k = 0; k < 32; k++) {
            float4 a0 = *(float4*)&Qs[k][tx * 8];
            float4 a1 = *(float4*)&Qs[k][tx * 8 + 4];
            float4 b0 = *(float4*)&KVs[k][ty * 8];
            float4 b1 = *(float4*)&KVs[k][ty * 8 + 4];
            float a[8]  = {a0.x, a0.y, a0.z, a0.w, a1.x, a1.y, a1.z, a1.w};
            float bf[8] = {b0.x, b0.y, b0.z, b0.w, b1.x, b1.y, b1.z, b1.w};
            const float ks = ksum_s[m0 + k];
            #pragma unroll
            for (int j = 0; j < 8; j++) den[j] = fmaf(a[j], ks, den[j]);
            #pragma unroll
            for (int i = 0; i < 8; i++)
                #pragma unroll
                for (int j = 0; j < 8; j++)
                    acc[i][j] = fmaf(bf[i], a[j], acc[i][j]);
        }
    }

    const float gm = gamma[0];
    float rn[8];
    #pragma unroll
    for (int j = 0; j < 8; j++) rn[j] = gm / den[j];

    #pragma unroll
    for (int i = 0; i < 8; i++) {
        const int c = c0 + ty * 8 + i;
        const size_t base = ((size_t)b * CC + c) * NN + n0 + tx * 8;
        float4 x0 = *(const float4*)(x + base);
        float4 x1 = *(const float4*)(x + base + 4);
        float4 o0, o1;
        o0.x = fmaf(acc[i][0], rn[0], x0.x);
        o0.y = fmaf(acc[i][1], rn[1], x0.y);
        o0.z = fmaf(acc[i][2], rn[2], x0.z);
        o0.w = fmaf(acc[i][3], rn[3], x0.w);
        o1.x = fmaf(acc[i][4], rn[4], x1.x);
        o1.y = fmaf(acc[i][5], rn[5], x1.y);
        o1.z = fmaf(acc[i][6], rn[6], x1.z);
        o1.w = fmaf(acc[i][7], rn[7], x1.w);
        *(float4*)(out + base)     = o0;
        *(float4*)(out + base + 4) = o1;
    }
}

// ---------------------------------------------------------------------------
extern "C" void kernel_launch(void* const* d_in, const int* in_sizes, int n_in,
                              void* d_out, int out_size) {
    const float* x     = (const float*)d_in[0];
    const float* Wq    = (const float*)d_in[1];
    const float* bq    = (const float*)d_in[2];
    const float* Wk    = (const float*)d_in[3];
    const float* bk    = (const float*)d_in[4];
    const float* Wv    = (const float*)d_in[5];
    const float* bv    = (const float*)d_in[6];
    const float* gamma = (const float*)d_in[7];
    float* out = (float*)d_out;

    k_zero<<<512, 512>>>();
    k_qk  <<<dim3(NN / 128, BB), 256>>>(x, Wq, bq, Wk, bk);
    k_kx  <<<dim3(NSPLIT, CC / 128, BB), 256>>>(x);
    k_kv  <<<dim3(CC / 64, BB), 256>>>(Wv, bv);
    k_out <<<dim3(CC / 128, NN / 128, BB), 256>>>(x, gamma, out);
}

// round 5
// speedup vs baseline: 2.5073x; 2.5073x over previous
#include <cuda_runtime.h>
#include <cstdint>

#define BB 8
#define CC 512
#define DD 64
#define NN 16384
#define PARAM 10.0f
#define EPS 1e-6f

__device__ float g_Q[BB*DD*NN];     // phi(Q) [b][m][n]
__device__ float g_Kt[BB*NN*DD];    // phi(K) transposed [b][n][m]
__device__ float g_Ksum[BB*DD];
__device__ float g_KXT[BB*CC*DD];   // (phiK @ x^T)^T [b][c][m]
__device__ float g_KVT[BB*CC*DD];   // KV^T (no bias) [b][c][m]

__device__ __forceinline__ float fmap(float t) {
    return t > 0.f ? fmaf(PARAM, t, 1.f) : __expf(PARAM * t);
}
__device__ __forceinline__ uint32_t tf(float x) {
    uint32_t u; asm("cvt.rna.tf32.f32 %0, %1;" : "=r"(u) : "f"(x)); return u;
}
#define MMA8(d, a, b0, b1) \
    asm volatile("mma.sync.aligned.m16n8k8.row.col.f32.tf32.tf32.f32 " \
        "{%0,%1,%2,%3}, {%4,%5,%6,%7}, {%8,%9}, {%0,%1,%2,%3};" \
        : "+f"((d)[0]), "+f"((d)[1]), "+f"((d)[2]), "+f"((d)[3]) \
        : "r"((a)[0]), "r"((a)[1]), "r"((a)[2]), "r"((a)[3]), "r"(b0), "r"(b1))

// ---------------------------------------------------------------------------
__global__ void k_zero() {
    int i = blockIdx.x*blockDim.x + threadIdx.x;
    if (i < BB*CC*DD) { g_KXT[i] = 0.f; g_KVT[i] = 0.f; }
    if (i < BB*DD) g_Ksum[i] = 0.f;
}

// ---------------------------------------------------------------------------
// k_qk: C[128m][128n] = [Wq;Wk](128x512) @ x_tile(512c x 128n). tf32 mma.
// Epilogue: bias+fmap; m<64 -> g_Q[m][n]; m>=64 -> g_Kt[n][m], Ksum atomics.
// ---------------------------------------------------------------------------
__global__ __launch_bounds__(256) void k_qk(const float* __restrict__ x,
        const float* __restrict__ Wq, const float* __restrict__ bq,
        const float* __restrict__ Wk, const float* __restrict__ bk) {
    __shared__ uint32_t As[128*36];   // [m][k(32)+4]
    __shared__ uint32_t Bs[32*136];   // [k(c)][n(128)+8]
    const int tid = threadIdx.x, w = tid>>5, lane = tid&31;
    const int gr = lane>>2, qt = lane&3;
    const int b = blockIdx.y, n0 = blockIdx.x*128;
    const int M0 = (w>>1)*32, N0 = (w&1)*64;
    const float* xb = x + (size_t)b*CC*NN;

    float4 pA[4], pB[4];
    #pragma unroll
    for (int i = 0; i < 4; i++) {
        int id = tid + i*256, r = id>>3, c4 = id&7;
        const float* Wr = r < 64 ? Wq + r*CC : Wk + (size_t)(r-64)*CC;
        pA[i] = *(const float4*)(Wr + c4*4);
    }
    #pragma unroll
    for (int i = 0; i < 4; i++) {
        int id = tid + i*256, r = id>>5, n4 = id&31;
        pB[i] = *(const float4*)(xb + (size_t)r*NN + n0 + n4*4);
    }
    float acc[2][8][4];
    #pragma unroll
    for (int mt = 0; mt < 2; mt++)
        #pragma unroll
        for (int nt = 0; nt < 8; nt++)
            #pragma unroll
            for (int i = 0; i < 4; i++) acc[mt][nt][i] = 0.f;

    for (int ci = 0; ci < 16; ci++) {
        #pragma unroll
        for (int i = 0; i < 4; i++) {
            int id = tid + i*256, r = id>>3, c4 = id&7;
            uint32_t* p = &As[r*36 + c4*4];
            p[0]=tf(pA[i].x); p[1]=tf(pA[i].y); p[2]=tf(pA[i].z); p[3]=tf(pA[i].w);
        }
        #pragma unroll
        for (int i = 0; i < 4; i++) {
            int id = tid + i*256, r = id>>5, n4 = id&31;
            uint32_t* p = &Bs[r*136 + n4*4];
            p[0]=tf(pB[i].x); p[1]=tf(pB[i].y); p[2]=tf(pB[i].z); p[3]=tf(pB[i].w);
        }
        __syncthreads();
        if (ci < 15) {
            int kc = (ci+1)*32;
            #pragma unroll
            for (int i = 0; i < 4; i++) {
                int id = tid + i*256, r = id>>3, c4 = id&7;
                const float* Wr = r < 64 ? Wq + r*CC : Wk + (size_t)(r-64)*CC;
                pA[i] = *(const float4*)(Wr + kc + c4*4);
            }
            #pragma unroll
            for (int i = 0; i < 4; i++) {
                int id = tid + i*256, r = id>>5, n4 = id&31;
                pB[i] = *(const float4*)(xb + (size_t)(kc+r)*NN + n0 + n4*4);
            }
        }
        #pragma unroll
        for (int k0 = 0; k0 < 32; k0 += 8) {
            uint32_t af[2][4], bf[8][2];
            #pragma unroll
            for (int mt = 0; mt < 2; mt++) {
                int base = (M0 + 16*mt + gr)*36 + k0 + qt;
                af[mt][0] = As[base];       af[mt][1] = As[base + 8*36];
                af[mt][2] = As[base + 4];   af[mt][3] = As[base + 8*36 + 4];
            }
            #pragma unroll
            for (int nt = 0; nt < 8; nt++) {
                int bb = (k0 + qt)*136 + N0 + 8*nt + gr;
                bf[nt][0] = Bs[bb]; bf[nt][1] = Bs[bb + 4*136];
            }
            #pragma unroll
            for (int mt = 0; mt < 2; mt++)
                #pragma unroll
                for (int nt = 0; nt < 8; nt++)
                    MMA8(acc[mt][nt], af[mt], bf[nt][0], bf[nt][1]);
        }
        __syncthreads();
    }

    #pragma unroll
    for (int mt = 0; mt < 2; mt++)
        #pragma unroll
        for (int h = 0; h < 2; h++) {
            const int m = M0 + 16*mt + 8*h + gr;
            const float bias = m < 64 ? __ldg(bq + m) : __ldg(bk + m - 64);
            float vv[8][2], ks = 0.f;
            #pragma unroll
            for (int nt = 0; nt < 8; nt++) {
                vv[nt][0] = fmap(acc[mt][nt][2*h]   + bias);
                vv[nt][1] = fmap(acc[mt][nt][2*h+1] + bias);
                ks += vv[nt][0] + vv[nt][1];
            }
            if (m < 64) {
                float* dst = g_Q + ((size_t)b*DD + m)*NN + n0 + N0;
                #pragma unroll
                for (int nt = 0; nt < 8; nt++)
                    *(float2*)(dst + 8*nt + 2*qt) = make_float2(vv[nt][0], vv[nt][1]);
            } else {
                const int mm = m - 64;
                #pragma unroll
                for (int nt = 0; nt < 8; nt++) {
                    int n = n0 + N0 + 8*nt + 2*qt;
                    float* dk = g_Kt + ((size_t)b*NN + n)*DD + mm;
                    dk[0] = vv[nt][0]; dk[DD] = vv[nt][1];
                }
                ks += __shfl_xor_sync(0xffffffffu, ks, 1);
                ks += __shfl_xor_sync(0xffffffffu, ks, 2);
                if (qt == 0) atomicAdd(&g_Ksum[b*DD + mm], ks);
            }
        }
}

// ---------------------------------------------------------------------------
// k_kx: KXT[128c][64m] += x_tile(c x n) @ phiK^T. A=x, B=g_Kt. Split-K=16.
// ---------------------------------------------------------------------------
__global__ __launch_bounds__(256) void k_kx(const float* __restrict__ x) {
    __shared__ uint32_t As[128*36];   // [c][k(32)+4]
    __shared__ uint32_t Bs[32*72];    // [k(n)][m(64)+8]
    const int tid = threadIdx.x, w = tid>>5, lane = tid&31;
    const int gr = lane>>2, qt = lane&3;
    const int c0 = blockIdx.x*128, b = blockIdx.z;
    const int nbase = blockIdx.y*(NN/16);
    const int M0 = (w>>1)*32, N0 = (w&1)*32;

    float4 pA[4], pB[2];
    #pragma unroll
    for (int i = 0; i < 4; i++) {
        int id = tid + i*256, r = id>>3, n4 = id&7;
        pA[i] = *(const float4*)(x + ((size_t)(b*CC + c0 + r))*NN + nbase + n4*4);
    }
    #pragma unroll
    for (int i = 0; i < 2; i++) {
        int id = tid + i*256, r = id>>4, m4 = id&15;
        pB[i] = *(const float4*)(g_Kt + ((size_t)b*NN + nbase + r)*DD + m4*4);
    }
    float acc[2][4][4];
    #pragma unroll
    for (int mt = 0; mt < 2; mt++)
        #pragma unroll
        for (int nt = 0; nt < 4; nt++)
            #pragma unroll
            for (int i = 0; i < 4; i++) acc[mt][nt][i] = 0.f;

    for (int ci = 0; ci < (NN/16)/32; ci++) {
        #pragma unroll
        for (int i = 0; i < 4; i++) {
            int id = tid + i*256, r = id>>3, n4 = id&7;
            uint32_t* p = &As[r*36 + n4*4];
            p[0]=tf(pA[i].x); p[1]=tf(pA[i].y); p[2]=tf(pA[i].z); p[3]=tf(pA[i].w);
        }
        #pragma unroll
        for (int i = 0; i < 2; i++) {
            int id = tid + i*256, r = id>>4, m4 = id&15;
            uint32_t* p = &Bs[r*72 + m4*4];
            p[0]=tf(pB[i].x); p[1]=tf(pB[i].y); p[2]=tf(pB[i].z); p[3]=tf(pB[i].w);
        }
        __syncthreads();
        if (ci < (NN/16)/32 - 1) {
            int kn = nbase + (ci+1)*32;
            #pragma unroll
            for (int i = 0; i < 4; i++) {
                int id = tid + i*256, r = id>>3, n4 = id&7;
                pA[i] = *(const float4*)(x + ((size_t)(b*CC + c0 + r))*NN + kn + n4*4);
            }
            #pragma unroll
            for (int i = 0; i < 2; i++) {
                int id = tid + i*256, r = id>>4, m4 = id&15;
                pB[i] = *(const float4*)(g_Kt + ((size_t)b*NN + kn + r)*DD + m4*4);
            }
        }
        #pragma unroll
        for (int k0 = 0; k0 < 32; k0 += 8) {
            uint32_t af[2][4], bf[4][2];
            #pragma unroll
            for (int mt = 0; mt < 2; mt++) {
                int base = (M0 + 16*mt + gr)*36 + k0 + qt;
                af[mt][0] = As[base];     af[mt][1] = As[base + 8*36];
                af[mt][2] = As[base + 4]; af[mt][3] = As[base + 8*36 + 4];
            }
            #pragma unroll
            for (int nt = 0; nt < 4; nt++) {
                int bb = (k0 + qt)*72 + N0 + 8*nt + gr;
                bf[nt][0] = Bs[bb]; bf[nt][1] = Bs[bb + 4*72];
            }
            #pragma unroll
            for (int mt = 0; mt < 2; mt++)
                #pragma unroll
                for (int nt = 0; nt < 4; nt++)
                    MMA8(acc[mt][nt], af[mt], bf[nt][0], bf[nt][1]);
        }
        __syncthreads();
    }
    #pragma unroll
    for (int mt = 0; mt < 2; mt++)
        #pragma unroll
        for (int h = 0; h < 2; h++) {
            int c = c0 + M0 + 16*mt + 8*h + gr;
            #pragma unroll
            for (int nt = 0; nt < 4; nt++) {
                int m = N0 + 8*nt + 2*qt;
                float* d = g_KXT + ((size_t)b*CC + c)*DD + m;
                atomicAdd(d,     acc[mt][nt][2*h]);
                atomicAdd(d + 1, acc[mt][nt][2*h+1]);
            }
        }
}

// ---------------------------------------------------------------------------
// k_kv (SIMT, split-K=4): KVT[c][m] += sum_{c'} Wv[c][c'] * KXT[c'][m]
// ---------------------------------------------------------------------------
__global__ __launch_bounds__(256) void k_kv(const float* __restrict__ Wv) {
    __shared__ float Ws[64*36];   // [c][c'(32)+4]
    __shared__ float Xs[32*68];   // [c'][m(64)+4]
    const int c0 = blockIdx.x*64, sp = blockIdx.y, b = blockIdx.z;
    const int tid = threadIdx.x, tx = tid&15, ty = tid>>4;

    float acc[4][4] = {};
    for (int kk = 0; kk < 4; kk++) {
        const int cp0 = sp*128 + kk*32;
        #pragma unroll
        for (int i = 0; i < 2; i++) {
            int id = tid + i*256, r = id>>3, q4 = id&7;
            *(float4*)&Ws[r*36 + q4*4] =
                *(const float4*)(Wv + (size_t)(c0 + r)*CC + cp0 + q4*4);
        }
        #pragma unroll
        for (int i = 0; i < 2; i++) {
            int id = tid + i*256, r = id>>4, m4 = id&15;
            *(float4*)&Xs[r*68 + m4*4] =
                *(const float4*)(g_KXT + ((size_t)(b*CC) + cp0 + r)*DD + m4*4);
        }
        __syncthreads();
        #pragma unroll
        for (int k = 0; k < 32; k++) {
            float a[4], bb[4];
            #pragma unroll
            for (int i = 0; i < 4; i++) a[i] = Ws[(ty*4+i)*36 + k];
            #pragma unroll
            for (int j = 0; j < 4; j++) bb[j] = Xs[k*68 + tx*4 + j];
            #pragma unroll
            for (int i = 0; i < 4; i++)
                #pragma unroll
                for (int j = 0; j < 4; j++)
                    acc[i][j] = fmaf(a[i], bb[j], acc[i][j]);
        }
        __syncthreads();
    }
    #pragma unroll
    for (int i = 0; i < 4; i++)
        #pragma unroll
        for (int j = 0; j < 4; j++)
            atomicAdd(&g_KVT[((size_t)b*CC + c0 + ty*4+i)*DD + tx*4 + j], acc[i][j]);
}

// ---------------------------------------------------------------------------
// k_out: C[64c][64n] = (KVT+bv*Ksum)[c][m] @ phiQ[m][n]; fused den + residual.
// ---------------------------------------------------------------------------
__global__ __launch_bounds__(256) void k_out(const float* __restrict__ x,
        const float* __restrict__ bv, const float* __restrict__ gamma,
        float* __restrict__ out) {
    __shared__ uint32_t As[64*68];   // [c][m(64)+4]
    __shared__ uint32_t Bs[64*72];   // [m][n(64)+8]
    __shared__ float dens[64], kss[64];
    const int tid = threadIdx.x, w = tid>>5, lane = tid&31;
    const int gr = lane>>2, qt = lane&3;
    const int c0 = blockIdx.x*64, n0 = blockIdx.y*64, b = blockIdx.z;
    const int M0 = (w>>1)*16, N0 = (w&1)*32;

    if (tid < 64) kss[tid] = g_Ksum[b*DD + tid];
    #pragma unroll
    for (int i = 0; i < 4; i++) {     // A = KVT + bv*Ksum
        int id = tid + i*256, r = id>>4, m4 = id&15;
        float4 v = *(const float4*)(g_KVT + ((size_t)b*CC + c0 + r)*DD + m4*4);
        float4 k4 = *(const float4*)(g_Ksum + b*DD + m4*4);
        float bvc = __ldg(bv + c0 + r);
        v.x = fmaf(bvc, k4.x, v.x); v.y = fmaf(bvc, k4.y, v.y);
        v.z = fmaf(bvc, k4.z, v.z); v.w = fmaf(bvc, k4.w, v.w);
        uint32_t* p = &As[r*68 + m4*4];
        p[0]=tf(v.x); p[1]=tf(v.y); p[2]=tf(v.z); p[3]=tf(v.w);
    }
    #pragma unroll
    for (int i = 0; i < 4; i++) {     // B = phiQ [m][n]
        int id = tid + i*256, r = id>>4, n4 = id&15;
        float4 v = *(const float4*)(g_Q + ((size_t)b*DD + r)*NN + n0 + n4*4);
        uint32_t* p = &Bs[r*72 + n4*4];
        p[0]=tf(v.x); p[1]=tf(v.y); p[2]=tf(v.z); p[3]=tf(v.w);
    }
    __syncthreads();
    if (tid < 64) {                   // den[n] = sum_m phiQ*(Ksum+eps)
        float d = 0.f;
        #pragma unroll 16
        for (int m = 0; m < 64; m++)
            d = fmaf(__uint_as_float(Bs[m*72 + tid]), kss[m] + EPS, d);
        dens[tid] = d;
    }
    float acc[4][4];
    #pragma unroll
    for (int nt = 0; nt < 4; nt++)
        #pragma unroll
        for (int i = 0; i < 4; i++) acc[nt][i] = 0.f;
    #pragma unroll
    for (int k0 = 0; k0 < 64; k0 += 8) {
        uint32_t af[4], bf[4][2];
        int base = (M0 + gr)*68 + k0 + qt;
        af[0] = As[base];     af[1] = As[base + 8*68];
        af[2] = As[base + 4]; af[3] = As[base + 8*68 + 4];
        #pragma unroll
        for (int nt = 0; nt < 4; nt++) {
            int bb = (k0 + qt)*72 + N0 + 8*nt + gr;
            bf[nt][0] = Bs[bb]; bf[nt][1] = Bs[bb + 4*72];
        }
        #pragma unroll
        for (int nt = 0; nt < 4; nt++)
            MMA8(acc[nt], af, bf[nt][0], bf[nt][1]);
    }
    __syncthreads();
    const float gm = gamma[0];
    #pragma unroll
    for (int h = 0; h < 2; h++) {
        const int c = c0 + M0 + 8*h + gr;
        #pragma unroll
        for (int nt = 0; nt < 4; nt++) {
            const int nl = N0 + 8*nt + 2*qt;
            const float rn0 = gm / dens[nl], rn1 = gm / dens[nl+1];
            const size_t bi = ((size_t)b*CC + c)*NN + n0 + nl;
            float2 xv = *(const float2*)(x + bi);
            float2 o;
            o.x = fmaf(acc[nt][2*h],   rn0, xv.x);
            o.y = fmaf(acc[nt][2*h+1], rn1, xv.y);
            *(float2*)(out + bi) = o;
        }
    }
}

// ---------------------------------------------------------------------------
extern "C" void kernel_launch(void* const* d_in, const int* in_sizes, int n_in,
                              void* d_out, int out_size) {
    const float* x     = (const float*)d_in[0];
    const float* Wq    = (const float*)d_in[1];
    const float* bq    = (const float*)d_in[2];
    const float* Wk    = (const float*)d_in[3];
    const float* bk    = (const float*)d_in[4];
    const float* Wv    = (const float*)d_in[5];
    const float* bv    = (const float*)d_in[6];
    const float* gamma = (const float*)d_in[7];
    float* out = (float*)d_out;

    k_zero<<<512, 512>>>();
    k_qk  <<<dim3(NN/128, BB), 256>>>(x, Wq, bq, Wk, bk);
    k_kx  <<<dim3(CC/128, 16, BB), 256>>>(x);
    k_kv  <<<dim3(CC/64, 4, BB), 256>>>(Wv);
    k_out <<<dim3(CC/64, NN/64, BB), 256>>>(x, bv, gamma, out);
}